// round 1
// baseline (speedup 1.0000x reference)
#include <cuda_runtime.h>

#define Bsz 4096
#define Tsz 256
#define Fsz 64
#define Hsz 16
#define Dsz 64
#define BB  32
#define NT  512

__device__ __forceinline__ float sigmoidf_(float v) {
    return 1.0f / (1.0f + __expf(-v));
}

__global__ __launch_bounds__(NT, 1)
void lstm_fused_kernel(const float* __restrict__ x,
                       const float* __restrict__ W,
                       const float* __restrict__ U,
                       const float* __restrict__ b,
                       const float* __restrict__ Wd,
                       const float* __restrict__ bd,
                       float* __restrict__ out)
{
    __shared__ float Ws[64][64];    // W row-major [F][4H]
    __shared__ float Us[16][64];    // U [H][4H]
    __shared__ float Wds[16][64];   // Wd [H][D]
    __shared__ float bds[64];
    __shared__ float xs[BB][64];    // current x tile
    __shared__ float zs[BB][64];    // z exchange
    __shared__ float hs[BB][16];    // hidden state

    const int tid = threadIdx.x;
    const int row = tid >> 4;       // 0..31  (warp owns rows 2w, 2w+1)
    const int u   = tid & 15;       // 0..15  (unit / column-quad index)

    for (int i = tid; i < 64 * 64; i += NT) ((float*)Ws)[i]  = W[i];
    for (int i = tid; i < 16 * 64; i += NT) ((float*)Us)[i]  = U[i];
    for (int i = tid; i < 16 * 64; i += NT) ((float*)Wds)[i] = Wd[i];
    if (tid < 64) bds[tid] = bd[tid];
    hs[row][u] = 0.0f;
    __syncthreads();

    const int grow = blockIdx.x * BB + row;
    const float* xrow = x + (size_t)grow * Tsz * Fsz + 4 * u;

    const float bi0 = b[4*u+0], bi1 = b[4*u+1], bi2 = b[4*u+2], bi3 = b[4*u+3];

    float c = 0.0f;
    float4 xn = *(const float4*)(xrow);   // prefetch t=0

    for (int t = 0; t < Tsz; t++) {
        *(float4*)&xs[row][4*u] = xn;
        __syncwarp();
        if (t + 1 < Tsz)
            xn = *(const float4*)(xrow + (size_t)(t + 1) * Fsz);

        // z[row][4u..4u+3] = b + x_row @ W + h_row @ U
        float a0 = bi0, a1 = bi1, a2 = bi2, a3 = bi3;
        #pragma unroll
        for (int f4 = 0; f4 < 16; f4++) {
            const float4 xv = *(const float4*)&xs[row][4*f4];
            float4 w;
            w = *(const float4*)&Ws[4*f4+0][4*u];
            a0 += xv.x*w.x; a1 += xv.x*w.y; a2 += xv.x*w.z; a3 += xv.x*w.w;
            w = *(const float4*)&Ws[4*f4+1][4*u];
            a0 += xv.y*w.x; a1 += xv.y*w.y; a2 += xv.y*w.z; a3 += xv.y*w.w;
            w = *(const float4*)&Ws[4*f4+2][4*u];
            a0 += xv.z*w.x; a1 += xv.z*w.y; a2 += xv.z*w.z; a3 += xv.z*w.w;
            w = *(const float4*)&Ws[4*f4+3][4*u];
            a0 += xv.w*w.x; a1 += xv.w*w.y; a2 += xv.w*w.z; a3 += xv.w*w.w;
        }
        #pragma unroll
        for (int j4 = 0; j4 < 4; j4++) {
            const float4 hv = *(const float4*)&hs[row][4*j4];
            float4 w;
            w = *(const float4*)&Us[4*j4+0][4*u];
            a0 += hv.x*w.x; a1 += hv.x*w.y; a2 += hv.x*w.z; a3 += hv.x*w.w;
            w = *(const float4*)&Us[4*j4+1][4*u];
            a0 += hv.y*w.x; a1 += hv.y*w.y; a2 += hv.y*w.z; a3 += hv.y*w.w;
            w = *(const float4*)&Us[4*j4+2][4*u];
            a0 += hv.z*w.x; a1 += hv.z*w.y; a2 += hv.z*w.z; a3 += hv.z*w.w;
            w = *(const float4*)&Us[4*j4+3][4*u];
            a0 += hv.w*w.x; a1 += hv.w*w.y; a2 += hv.w*w.z; a3 += hv.w*w.w;
        }
        *(float4*)&zs[row][4*u] = make_float4(a0, a1, a2, a3);
        __syncwarp();

        // Keras gate order: i, f, g(candidate, relu), o
        const float ig = sigmoidf_(zs[row][u]);
        const float fg = sigmoidf_(zs[row][u + 16]);
        const float gg = fmaxf(zs[row][u + 32], 0.0f);
        const float og = sigmoidf_(zs[row][u + 48]);
        c = fg * c + ig * gg;
        hs[row][u] = og * fmaxf(c, 0.0f);   // output activation = relu
    }
    __syncwarp();

    // Dense(D=64, sigmoid) + row sum-normalize
    float d0 = bds[4*u+0], d1 = bds[4*u+1], d2 = bds[4*u+2], d3 = bds[4*u+3];
    #pragma unroll
    for (int j = 0; j < 16; j++) {
        const float hv = hs[row][j];
        const float4 w = *(const float4*)&Wds[j][4*u];
        d0 += hv*w.x; d1 += hv*w.y; d2 += hv*w.z; d3 += hv*w.w;
    }
    d0 = sigmoidf_(d0); d1 = sigmoidf_(d1); d2 = sigmoidf_(d2); d3 = sigmoidf_(d3);
    float s = d0 + d1 + d2 + d3;
    #pragma unroll
    for (int off = 1; off < 16; off <<= 1)      // reduce within the 16-lane row group
        s += __shfl_xor_sync(0xffffffffu, s, off);
    const float inv = 1.0f / s;
    *(float4*)&out[(size_t)grow * Dsz + 4*u] =
        make_float4(d0*inv, d1*inv, d2*inv, d3*inv);
}

extern "C" void kernel_launch(void* const* d_in, const int* in_sizes, int n_in,
                              void* d_out, int out_size) {
    const float* x  = (const float*)d_in[0];
    const float* W  = (const float*)d_in[1];
    const float* U  = (const float*)d_in[2];
    const float* b  = (const float*)d_in[3];
    const float* Wd = (const float*)d_in[4];
    const float* bd = (const float*)d_in[5];
    float* out = (float*)d_out;
    lstm_fused_kernel<<<Bsz / BB, NT>>>(x, W, U, b, Wd, bd, out);
}

// round 6
// speedup vs baseline: 2.1554x; 2.1554x over previous
#include <cuda_runtime.h>

#define Bsz 4096
#define Tsz 256
#define Fsz 64
#define Hsz 16
#define Dsz 64
#define BB  32      // rows per block
#define NT  128     // threads per block (4 warps, warp owns 8 rows)

// ---------- packed f32x2 helpers ----------
__device__ __forceinline__ unsigned long long ffma2_(unsigned long long a,
                                                     unsigned long long b,
                                                     unsigned long long c) {
    unsigned long long d;
    asm("fma.rn.f32x2 %0, %1, %2, %3;" : "=l"(d) : "l"(a), "l"(b), "l"(c));
    return d;
}
__device__ __forceinline__ unsigned long long pack2_(float lo, float hi) {
    unsigned long long d;
    asm("mov.b64 %0, {%1, %2};" : "=l"(d) : "f"(lo), "f"(hi));
    return d;
}
__device__ __forceinline__ float2 unpack2_(unsigned long long v) {
    float2 r;
    asm("mov.b64 {%0, %1}, %2;" : "=f"(r.x), "=f"(r.y) : "l"(v));
    return r;
}
__device__ __forceinline__ float sigmoidf_(float v) {
    return __fdividef(1.0f, 1.0f + __expf(-v));
}

__global__ __launch_bounds__(NT, 1)
void lstm_fused2_kernel(const float* __restrict__ x,
                        const float* __restrict__ W,
                        const float* __restrict__ U,
                        const float* __restrict__ b,
                        const float* __restrict__ Wd,
                        const float* __restrict__ bd,
                        float* __restrict__ out)
{
    __shared__ float Ws[64][68];    // W [k][4H], padded stride (16B multiple)
    __shared__ float xs[BB][68];    // x tile for current t
    __shared__ float zs[BB][68];    // z exchange
    __shared__ float hs[16][36];    // h state: [unit][row]

    const int tid  = threadIdx.x;
    const int warp = tid >> 5;
    const int lane = tid & 31;
    const int rs   = lane >> 4;       // 0..1 row-slice within warp
    const int u    = lane & 15;       // 0..15 col-quad index
    const int wrow = warp * 8 + rs * 4;            // first of this thread's 4 rows
    const size_t grow0 = (size_t)blockIdx.x * BB + wrow;

    // cooperative load of W into smem (4096 floats = 1024 float4, 8 per thread)
    for (int idx = tid; idx < 1024; idx += NT) {
        int k  = idx >> 4;
        int c4 = idx & 15;
        *(float4*)&Ws[k][4 * c4] = *(const float4*)&W[k * 64 + 4 * c4];
    }
    for (int i = tid; i < 16 * 36; i += NT) ((float*)hs)[i] = 0.0f;
    __syncthreads();

    // U slice [16 k][cols 4u..4u+3] in registers as f32x2 pairs
    ulonglong2 Ud[16];
    #pragma unroll
    for (int k = 0; k < 16; k++)
        Ud[k] = *(const ulonglong2*)&U[k * 64 + 4 * u];

    // bias for this thread's 4 cols
    const float4 bv4 = *(const float4*)&b[4 * u];
    const unsigned long long b01 = pack2_(bv4.x, bv4.y);
    const unsigned long long b23 = pack2_(bv4.z, bv4.w);

    // x loading role: thread loads row (tid>>2) [within the block],
    // f range [16*(tid&3), +16). (tid>>2) for tid in warp w spans
    // exactly rows 8w..8w+7 => warp loads only its own rows.
    const int lrow = tid >> 2;
    const int f0   = (tid & 3) * 16;
    const float* xsrc = x + ((size_t)blockIdx.x * BB + lrow) * Tsz * Fsz + f0;

    float4 xn[4];
    #pragma unroll
    for (int j = 0; j < 4; j++)
        xn[j] = *(const float4*)(xsrc + 4 * j);            // prefetch t=0

    float c0 = 0.f, c1 = 0.f, c2 = 0.f, c3 = 0.f;

    for (int t = 0; t < Tsz; t++) {
        // stage this t's x tile (warp-private rows)
        #pragma unroll
        for (int j = 0; j < 4; j++)
            *(float4*)&xs[lrow][f0 + 4 * j] = xn[j];
        __syncwarp();
        if (t + 1 < Tsz) {
            #pragma unroll
            for (int j = 0; j < 4; j++)
                xn[j] = *(const float4*)(xsrc + (size_t)(t + 1) * Fsz + 4 * j);
        }

        // ---- z[4 rows][4 cols] = b + x@W + h@U ----
        unsigned long long a[4][2];
        #pragma unroll
        for (int i = 0; i < 4; i++) { a[i][0] = b01; a[i][1] = b23; }

        #pragma unroll 4
        for (int k4 = 0; k4 < 16; k4++) {
            float4 xq[4];
            #pragma unroll
            for (int i = 0; i < 4; i++)
                xq[i] = *(const float4*)&xs[wrow + i][4 * k4];
            #pragma unroll
            for (int kk = 0; kk < 4; kk++) {
                const ulonglong2 wv = *(const ulonglong2*)&Ws[4 * k4 + kk][4 * u];
                const float xv0 = (&xq[0].x)[kk];
                const float xv1 = (&xq[1].x)[kk];
                const float xv2 = (&xq[2].x)[kk];
                const float xv3 = (&xq[3].x)[kk];
                unsigned long long hd;
                hd = pack2_(xv0, xv0);
                a[0][0] = ffma2_(hd, wv.x, a[0][0]); a[0][1] = ffma2_(hd, wv.y, a[0][1]);
                hd = pack2_(xv1, xv1);
                a[1][0] = ffma2_(hd, wv.x, a[1][0]); a[1][1] = ffma2_(hd, wv.y, a[1][1]);
                hd = pack2_(xv2, xv2);
                a[2][0] = ffma2_(hd, wv.x, a[2][0]); a[2][1] = ffma2_(hd, wv.y, a[2][1]);
                hd = pack2_(xv3, xv3);
                a[3][0] = ffma2_(hd, wv.x, a[3][0]); a[3][1] = ffma2_(hd, wv.y, a[3][1]);
            }
        }
        #pragma unroll
        for (int k = 0; k < 16; k++) {
            const float4 hv = *(const float4*)&hs[k][wrow];
            const ulonglong2 uk = Ud[k];
            unsigned long long hd;
            hd = pack2_(hv.x, hv.x);
            a[0][0] = ffma2_(hd, uk.x, a[0][0]); a[0][1] = ffma2_(hd, uk.y, a[0][1]);
            hd = pack2_(hv.y, hv.y);
            a[1][0] = ffma2_(hd, uk.x, a[1][0]); a[1][1] = ffma2_(hd, uk.y, a[1][1]);
            hd = pack2_(hv.z, hv.z);
            a[2][0] = ffma2_(hd, uk.x, a[2][0]); a[2][1] = ffma2_(hd, uk.y, a[2][1]);
            hd = pack2_(hv.w, hv.w);
            a[3][0] = ffma2_(hd, uk.x, a[3][0]); a[3][1] = ffma2_(hd, uk.y, a[3][1]);
        }
        #pragma unroll
        for (int i = 0; i < 4; i++) {
            float2 lo = unpack2_(a[i][0]);
            float2 hi = unpack2_(a[i][1]);
            *(float4*)&zs[wrow + i][4 * u] = make_float4(lo.x, lo.y, hi.x, hi.y);
        }
        __syncwarp();

        // ---- gates: this thread's 4 rows, unit u ----
        {
            float zi, zf, zg, zo, ig, fg, gg, og;
            #define GATE(i, cc)                                              \
                zi = zs[wrow + i][u];      zf = zs[wrow + i][u + 16];        \
                zg = zs[wrow + i][u + 32]; zo = zs[wrow + i][u + 48];        \
                ig = sigmoidf_(zi); fg = sigmoidf_(zf);                      \
                gg = fmaxf(zg, 0.0f); og = sigmoidf_(zo);                    \
                cc = fg * cc + ig * gg;                                      \
                hs[u][wrow + i] = og * fmaxf(cc, 0.0f);
            GATE(0, c0) GATE(1, c1) GATE(2, c2) GATE(3, c3)
            #undef GATE
        }
        __syncwarp();
    }

    // ---- dense(D=64, sigmoid) + sum-normalize ----
    float d[4][4];
    {
        const float4 bdv = *(const float4*)&bd[4 * u];
        #pragma unroll
        for (int i = 0; i < 4; i++) {
            d[i][0] = bdv.x; d[i][1] = bdv.y; d[i][2] = bdv.z; d[i][3] = bdv.w;
        }
    }
    #pragma unroll
    for (int k = 0; k < 16; k++) {
        const float4 hv = *(const float4*)&hs[k][wrow];
        const float4 wv = *(const float4*)&Wd[k * 64 + 4 * u];
        d[0][0] += hv.x * wv.x; d[0][1] += hv.x * wv.y; d[0][2] += hv.x * wv.z; d[0][3] += hv.x * wv.w;
        d[1][0] += hv.y * wv.x; d[1][1] += hv.y * wv.y; d[1][2] += hv.y * wv.z; d[1][3] += hv.y * wv.w;
        d[2][0] += hv.z * wv.x; d[2][1] += hv.z * wv.y; d[2][2] += hv.z * wv.z; d[2][3] += hv.z * wv.w;
        d[3][0] += hv.w * wv.x; d[3][1] += hv.w * wv.y; d[3][2] += hv.w * wv.z; d[3][3] += hv.w * wv.w;
    }
    #pragma unroll
    for (int i = 0; i < 4; i++) {
        #pragma unroll
        for (int j = 0; j < 4; j++) d[i][j] = sigmoidf_(d[i][j]);
        float s = d[i][0] + d[i][1] + d[i][2] + d[i][3];
        #pragma unroll
        for (int off = 1; off < 16; off <<= 1)   // reduce over the 16 u-lanes
            s += __shfl_xor_sync(0xffffffffu, s, off);
        const float inv = __fdividef(1.0f, s);
        *(float4*)&out[(grow0 + i) * 64 + 4 * u] =
            make_float4(d[i][0] * inv, d[i][1] * inv, d[i][2] * inv, d[i][3] * inv);
    }
}

extern "C" void kernel_launch(void* const* d_in, const int* in_sizes, int n_in,
                              void* d_out, int out_size) {
    const float* x  = (const float*)d_in[0];
    const float* W  = (const float*)d_in[1];
    const float* U  = (const float*)d_in[2];
    const float* b  = (const float*)d_in[3];
    const float* Wd = (const float*)d_in[4];
    const float* bd = (const float*)d_in[5];
    float* out = (float*)d_out;
    lstm_fused2_kernel<<<Bsz / BB, NT>>>(x, W, U, b, Wd, bd, out);
}